// round 15
// baseline (speedup 1.0000x reference)
#include <cuda_runtime.h>
#include <cuda_fp16.h>
#include <mma.h>
#include <math.h>

#define NNODES 50000
#define NEDGES 800000
#define HC 128
#define SLOTS 64            // max degree capacity (Poisson λ=16; P(overflow) < 1e-8)
#define LOG2E 1.4426950408889634f

// ---------------- scratch (device globals; no allocation allowed) ----------
__device__ __align__(128) __half g_xl1h[NNODES * HC];  // gathered operand, fp16
__device__ __align__(128) float  g_xr1 [NNODES * HC];
__device__ __align__(128) __half g_h1h [NNODES * HC];  // layer-1 output (fp16, GEMM A)
__device__ __align__(128) __half g_xl2h[NNODES * HC];  // gathered operand, fp16
__device__ __align__(128) float  g_xr2 [NNODES * HC];
__device__ __align__(128) __half g_Wl2h[HC * HC];      // fp16 weights for HMMA
__device__ __align__(128) __half g_Wr2h[HC * HC];
// bucketed adjacency (built in ONE pass; no scan needed)
__device__ __align__(128) int   g_cnt[NNODES];         // per-node degree / cursor
__device__ __align__(128) int2  g_edge[NNODES * SLOTS];// (src, ea bits) per dst bucket

// ---------------- helpers ---------------------------------------------------
__device__ __forceinline__ float lrelu(float v) { return v >= 0.f ? v : 0.2f * v; }
__device__ __forceinline__ float eluf(float v)  { return v > 0.f ? v : expm1f(v); }

// load 4 halves (one uint2) and expand to float4
__device__ __forceinline__ float4 ld_half4(const __half* base, int idx4) {
    uint2 raw = ((const uint2*)base)[idx4];
    float2 lo = __half22float2(*(__half2*)&raw.x);
    float2 hi = __half22float2(*(__half2*)&raw.y);
    return make_float4(lo.x, lo.y, hi.x, hi.y);
}

// ---------------- bucket build ----------------------------------------------
__global__ void k_zero_cnt() {
    int i = blockIdx.x * blockDim.x + threadIdx.x;
    int i4 = i * 4;
    if (i4 + 3 < NNODES) {
        *(int4*)&g_cnt[i4] = make_int4(0, 0, 0, 0);
    } else if (i4 < NNODES) {
        for (int j = i4; j < NNODES; j++) g_cnt[j] = 0;
    }
}

// single pass: count + place (replaces hist + 3 scan stages + scatter)
__global__ void k_bucket(const int* __restrict__ ei, const float* __restrict__ ea) {
    int e = blockIdx.x * blockDim.x + threadIdx.x;
    if (e >= NEDGES) return;
    int d = ei[NEDGES + e];
    int pos = atomicAdd(&g_cnt[d], 1);
    g_edge[d * SLOTS + pos] = make_int2(ei[e], __float_as_int(ea[e]));
}

// ---------------- weight fp16 conversion (tiny) ------------------------------
__global__ void k_wcvt(const float* __restrict__ Wl, const float* __restrict__ Wr) {
    int i = blockIdx.x * blockDim.x + threadIdx.x;
    if (i < HC * HC) {
        g_Wl2h[i] = __float2half_rn(Wl[i]);
        g_Wr2h[i] = __float2half_rn(Wr[i]);
    }
}

// ---------------- layer 1 linear: x[N,16] -> xl1(fp16), xr1(fp32) ----------
#define L1_NODES 32
__global__ __launch_bounds__(128) void k_lin1(
    const float* __restrict__ x,
    const float* __restrict__ Wl, const float* __restrict__ bl,
    const float* __restrict__ Wr, const float* __restrict__ br)
{
    __shared__ float sWl[128 * 17];
    __shared__ float sWr[128 * 17];
    __shared__ float xs[L1_NODES * 16];
    int tid = threadIdx.x;
    int nb = blockIdx.x * L1_NODES;

    #pragma unroll
    for (int k = 0; k < 16; k++) {
        sWl[tid * 17 + k] = Wl[tid * 16 + k];
        sWr[tid * 17 + k] = Wr[tid * 16 + k];
    }
    {
        int node = nb + (tid >> 2);
        float4 v = make_float4(0.f, 0.f, 0.f, 0.f);
        if (node < NNODES) v = *(const float4*)&x[(long)node * 16 + (tid & 3) * 4];
        ((float4*)xs)[tid] = v;
    }
    __syncthreads();

    float bL = bl[tid], bR = br[tid];
    for (int i = 0; i < L1_NODES; i++) {
        int n = nb + i;
        if (n >= NNODES) break;
        float aL = bL, aR = bR;
        #pragma unroll
        for (int k = 0; k < 16; k++) {
            float xv = xs[i * 16 + k];
            aL += xv * sWl[tid * 17 + k];
            aR += xv * sWr[tid * 17 + k];
        }
        g_xl1h[(long)n * HC + tid] = __float2half_rn(aL);
        g_xr1 [(long)n * HC + tid] = aR;
    }
}

// ---------------- layer 1 aggregation: warp per dst node, 4-edge unroll -----
__global__ __launch_bounds__(256) void k_agg1(
    const float* __restrict__ We, const float* __restrict__ att,
    const float* __restrict__ b1)
{
    int n = blockIdx.x * 8 + (threadIdx.x >> 5);
    int t = threadIdx.x & 31;
    if (n >= NNODES) return;

    float4 b  = ((const float4*)g_xr1)[n * 32 + t];
    float4 wv = ((const float4*)We)[t];
    float4 av = ((const float4*)att)[t];
    av.x *= LOG2E; av.y *= LOG2E; av.z *= LOG2E; av.w *= LOG2E;

    float den = 0.f;
    float ax = 0.f, ay = 0.f, az = 0.f, aw = 0.f;

    int k0 = n * SLOTS, k1 = k0 + g_cnt[n];
    int k = k0;

    #define L1_LOGIT(a, e) \
        (lrelu(a.x + b.x + e * wv.x) * av.x + lrelu(a.y + b.y + e * wv.y) * av.y \
       + lrelu(a.z + b.z + e * wv.z) * av.z + lrelu(a.w + b.w + e * wv.w) * av.w)
    #define L1_RED(p) \
        p += __shfl_xor_sync(0xffffffffu, p, 4); \
        p += __shfl_xor_sync(0xffffffffu, p, 2); \
        p += __shfl_xor_sync(0xffffffffu, p, 1);

    for (; k + 3 < k1; k += 4) {
        int2 E0 = g_edge[k], E1 = g_edge[k+1], E2 = g_edge[k+2], E3 = g_edge[k+3];
        float eA = __int_as_float(E0.y), eB = __int_as_float(E1.y);
        float eC = __int_as_float(E2.y), eD = __int_as_float(E3.y);
        float4 a0 = ld_half4(g_xl1h, E0.x * 32 + t);
        float4 a1 = ld_half4(g_xl1h, E1.x * 32 + t);
        float4 a2 = ld_half4(g_xl1h, E2.x * 32 + t);
        float4 a3 = ld_half4(g_xl1h, E3.x * 32 + t);
        float p0 = L1_LOGIT(a0, eA);
        float p1 = L1_LOGIT(a1, eB);
        float p2 = L1_LOGIT(a2, eC);
        float p3 = L1_LOGIT(a3, eD);
        L1_RED(p0) L1_RED(p1) L1_RED(p2) L1_RED(p3)
        float e0 = exp2f(p0), e1 = exp2f(p1), e2 = exp2f(p2), e3 = exp2f(p3);
        den += (e0 + e1) + (e2 + e3);
        ax += e0 * a0.x + e1 * a1.x + e2 * a2.x + e3 * a3.x;
        ay += e0 * a0.y + e1 * a1.y + e2 * a2.y + e3 * a3.y;
        az += e0 * a0.z + e1 * a1.z + e2 * a2.z + e3 * a3.z;
        aw += e0 * a0.w + e1 * a1.w + e2 * a2.w + e3 * a3.w;
    }
    for (; k < k1; k++) {
        int2 E = g_edge[k];
        float e = __int_as_float(E.y);
        float4 a0 = ld_half4(g_xl1h, E.x * 32 + t);
        float p0 = L1_LOGIT(a0, e);
        L1_RED(p0)
        float e0 = exp2f(p0);
        den += e0;
        ax += e0 * a0.x; ay += e0 * a0.y; az += e0 * a0.z; aw += e0 * a0.w;
    }
    #undef L1_LOGIT
    #undef L1_RED

    float inv = den > 0.f ? 1.f / den : 0.f;
    float4 bb = ((const float4*)b1)[t];
    float o0 = eluf(ax * inv + bb.x);
    float o1 = eluf(ay * inv + bb.y);
    float o2 = eluf(az * inv + bb.z);
    float o3 = eluf(aw * inv + bb.w);
    __half2 ha = __floats2half2_rn(o0, o1);
    __half2 hb = __floats2half2_rn(o2, o3);
    uint2 pk;
    pk.x = *(unsigned*)&ha; pk.y = *(unsigned*)&hb;
    ((uint2*)g_h1h)[n * 32 + t] = pk;
}

// ---------------- layer 2 linear: HMMA (wmma) dual GEMM ---------------------
__global__ __launch_bounds__(256) void k_lin2_wmma(
    const float* __restrict__ bl, const float* __restrict__ br)
{
    using namespace nvcuda::wmma;
    __shared__ float slab[8][16][68];

    int warp = threadIdx.x >> 5, lane = threadIdx.x & 31;
    int rg = warp & 3, cg = warp >> 2;
    int row0 = blockIdx.x * 64 + rg * 16;
    if (row0 >= NNODES) return;        // NNODES % 16 == 0, frags never straddle
    int colbase = cg * 64;

    fragment<accumulator, 16, 16, 16, float> cL[4], cR[4];
    #pragma unroll
    for (int j = 0; j < 4; j++) { fill_fragment(cL[j], 0.f); fill_fragment(cR[j], 0.f); }

    #pragma unroll
    for (int k0 = 0; k0 < 128; k0 += 16) {
        fragment<matrix_a, 16, 16, 16, __half, row_major> a;
        load_matrix_sync(a, g_h1h + (long)row0 * 128 + k0, 128);
        #pragma unroll
        for (int j = 0; j < 4; j++) {
            fragment<matrix_b, 16, 16, 16, __half, col_major> bfrag;
            load_matrix_sync(bfrag, g_Wl2h + (long)(colbase + j * 16) * 128 + k0, 128);
            mma_sync(cL[j], a, bfrag, cL[j]);
            load_matrix_sync(bfrag, g_Wr2h + (long)(colbase + j * 16) * 128 + k0, 128);
            mma_sync(cR[j], a, bfrag, cR[j]);
        }
    }

    // epilogue L -> xl2 (fp16)
    #pragma unroll
    for (int j = 0; j < 4; j++)
        store_matrix_sync(&slab[warp][0][j * 16], cL[j], 68, mem_row_major);
    __syncwarp();
    for (int i = lane; i < 16 * 32; i += 32) {      // half2 elements
        int r = i >> 5, c2 = (i & 31) * 2;
        float v0 = slab[warp][r][c2]     + bl[colbase + c2];
        float v1 = slab[warp][r][c2 + 1] + bl[colbase + c2 + 1];
        __half2 h = __floats2half2_rn(v0, v1);
        *(__half2*)&g_xl2h[(long)(row0 + r) * 128 + colbase + c2] = h;
    }
    __syncwarp();

    // epilogue R -> xr2 (fp32)
    #pragma unroll
    for (int j = 0; j < 4; j++)
        store_matrix_sync(&slab[warp][0][j * 16], cR[j], 68, mem_row_major);
    __syncwarp();
    for (int i = lane; i < 16 * 32; i += 32) {      // float2 elements
        int r = i >> 5, c2 = (i & 31) * 2;
        float2 v;
        v.x = slab[warp][r][c2]     + br[colbase + c2];
        v.y = slab[warp][r][c2 + 1] + br[colbase + c2 + 1];
        *(float2*)&g_xr2[(long)(row0 + r) * 128 + colbase + c2] = v;
    }
}

// ---------------- layer 2 aggregation + MLP head, fused (warp per node) -----
__global__ __launch_bounds__(256) void k_agg2_mlp(
    const float* __restrict__ We, const float* __restrict__ att,
    const float* __restrict__ b2,
    const float* __restrict__ W1, const float* __restrict__ c1,
    const float* __restrict__ W2, const float* __restrict__ c2,
    const float* __restrict__ W3, const float* __restrict__ c3,
    float* __restrict__ out)
{
    __shared__ float sW1[32][129];
    __shared__ float sW2[32][33];
    __shared__ float sW3[2][32];
    __shared__ float sh[8][128];
    int tid = threadIdx.x;
    for (int i = tid; i < 32 * 128; i += 256) sW1[i >> 7][i & 127] = W1[i];
    for (int i = tid; i < 32 * 32; i += 256) sW2[i >> 5][i & 31] = W2[i];
    if (tid < 64) sW3[tid >> 5][tid & 31] = W3[tid];
    __syncthreads();

    int w = tid >> 5, t = tid & 31;
    int n = blockIdx.x * 8 + w;
    if (n >= NNODES) return;

    float4 b  = ((const float4*)g_xr2)[n * 32 + t];
    float4 wv = ((const float4*)We)[t];
    float4 av = ((const float4*)att)[t];
    av.x *= LOG2E; av.y *= LOG2E; av.z *= LOG2E; av.w *= LOG2E;

    float den = 0.f;
    float ax = 0.f, ay = 0.f, az = 0.f, aw = 0.f;

    int k0 = n * SLOTS, k1 = k0 + g_cnt[n];
    int k = k0;

    #define L2_LOGIT(a, e) \
        (lrelu(a.x + b.x + e * wv.x) * av.x + lrelu(a.y + b.y + e * wv.y) * av.y \
       + lrelu(a.z + b.z + e * wv.z) * av.z + lrelu(a.w + b.w + e * wv.w) * av.w)
    #define L2_RED(p) { \
        p += __shfl_xor_sync(0xffffffffu, p, 16); \
        p += __shfl_xor_sync(0xffffffffu, p, 8); \
        p += __shfl_xor_sync(0xffffffffu, p, 4); \
        p += __shfl_xor_sync(0xffffffffu, p, 2); \
        p += __shfl_xor_sync(0xffffffffu, p, 1); }

    for (; k + 3 < k1; k += 4) {
        int2 E0 = g_edge[k], E1 = g_edge[k+1], E2 = g_edge[k+2], E3 = g_edge[k+3];
        float eA = __int_as_float(E0.y), eB = __int_as_float(E1.y);
        float eC = __int_as_float(E2.y), eD = __int_as_float(E3.y);
        float4 a0 = ld_half4(g_xl2h, E0.x * 32 + t);
        float4 a1 = ld_half4(g_xl2h, E1.x * 32 + t);
        float4 a2 = ld_half4(g_xl2h, E2.x * 32 + t);
        float4 a3 = ld_half4(g_xl2h, E3.x * 32 + t);
        float p0 = L2_LOGIT(a0, eA);
        float p1 = L2_LOGIT(a1, eB);
        float p2 = L2_LOGIT(a2, eC);
        float p3 = L2_LOGIT(a3, eD);
        L2_RED(p0) L2_RED(p1) L2_RED(p2) L2_RED(p3)
        float e0 = exp2f(p0), e1 = exp2f(p1), e2 = exp2f(p2), e3 = exp2f(p3);
        den += (e0 + e1) + (e2 + e3);
        ax += e0 * a0.x + e1 * a1.x + e2 * a2.x + e3 * a3.x;
        ay += e0 * a0.y + e1 * a1.y + e2 * a2.y + e3 * a3.y;
        az += e0 * a0.z + e1 * a1.z + e2 * a2.z + e3 * a3.z;
        aw += e0 * a0.w + e1 * a1.w + e2 * a2.w + e3 * a3.w;
    }
    for (; k < k1; k++) {
        int2 E = g_edge[k];
        float e = __int_as_float(E.y);
        float4 a0 = ld_half4(g_xl2h, E.x * 32 + t);
        float p0 = L2_LOGIT(a0, e);
        L2_RED(p0)
        float e0 = exp2f(p0);
        den += e0;
        ax += e0 * a0.x; ay += e0 * a0.y; az += e0 * a0.z; aw += e0 * a0.w;
    }
    #undef L2_LOGIT
    #undef L2_RED

    float inv = den > 0.f ? 1.f / den : 0.f;
    float4 bb = ((const float4*)b2)[t];
    sh[w][t * 4 + 0] = eluf(ax * inv + bb.x);
    sh[w][t * 4 + 1] = eluf(ay * inv + bb.y);
    sh[w][t * 4 + 2] = eluf(az * inv + bb.z);
    sh[w][t * 4 + 3] = eluf(aw * inv + bb.w);
    __syncwarp();

    float t1 = c1[t];
    #pragma unroll
    for (int kk = 0; kk < 128; kk++) t1 += sh[w][kk] * sW1[t][kk];
    t1 = fmaxf(t1, 0.f);

    float t2 = c2[t];
    #pragma unroll
    for (int kk = 0; kk < 32; kk++) t2 += __shfl_sync(0xffffffffu, t1, kk) * sW2[t][kk];
    t2 = fmaxf(t2, 0.f);

    float s0 = t2 * sW3[0][t];
    float s1 = t2 * sW3[1][t];
    #pragma unroll
    for (int o = 16; o; o >>= 1) {
        s0 += __shfl_down_sync(0xffffffffu, s0, o);
        s1 += __shfl_down_sync(0xffffffffu, s1, o);
    }
    if (t == 0) {
        out[(long)n * 2 + 0] = s0 + c3[0];
        out[(long)n * 2 + 1] = s1 + c3[1];
    }
}

// ---------------- launch ----------------------------------------------------
extern "C" void kernel_launch(void* const* d_in, const int* in_sizes, int n_in,
                              void* d_out, int out_size)
{
    const float* x    = (const float*)d_in[0];
    const int*   ei   = (const int*)d_in[1];
    const float* ea   = (const float*)d_in[2];
    const float* Wl1  = (const float*)d_in[3];
    const float* bl1  = (const float*)d_in[4];
    const float* Wr1  = (const float*)d_in[5];
    const float* br1  = (const float*)d_in[6];
    const float* We1  = (const float*)d_in[7];
    const float* att1 = (const float*)d_in[8];
    const float* b1   = (const float*)d_in[9];
    const float* Wl2  = (const float*)d_in[10];
    const float* bl2  = (const float*)d_in[11];
    const float* Wr2  = (const float*)d_in[12];
    const float* br2  = (const float*)d_in[13];
    const float* We2  = (const float*)d_in[14];
    const float* att2 = (const float*)d_in[15];
    const float* b2   = (const float*)d_in[16];
    const float* W1   = (const float*)d_in[17];
    const float* c1   = (const float*)d_in[18];
    const float* W2   = (const float*)d_in[19];
    const float* c2   = (const float*)d_in[20];
    const float* W3   = (const float*)d_in[21];
    const float* c3   = (const float*)d_in[22];
    float* out = (float*)d_out;

    // fork a side stream: bucket build (default stream) || wcvt+lin1 (side)
    cudaStream_t s2;
    cudaStreamCreateWithFlags(&s2, cudaStreamNonBlocking);
    cudaEvent_t evFork, evJoin;
    cudaEventCreateWithFlags(&evFork, cudaEventDisableTiming);
    cudaEventCreateWithFlags(&evJoin, cudaEventDisableTiming);

    cudaEventRecord(evFork, 0);
    cudaStreamWaitEvent(s2, evFork, 0);

    // bucket build on the capture-origin (default) stream: 2 launches total
    k_zero_cnt<<<(NNODES / 4 + 255) / 256, 256>>>();
    k_bucket<<<(NEDGES + 255) / 256, 256>>>(ei, ea);

    // independent work on the side stream
    k_wcvt<<<(HC * HC + 255) / 256, 256, 0, s2>>>(Wl2, Wr2);
    k_lin1<<<(NNODES + L1_NODES - 1) / L1_NODES, 128, 0, s2>>>(x, Wl1, bl1, Wr1, br1);

    cudaEventRecord(evJoin, s2);
    cudaStreamWaitEvent(0, evJoin, 0);

    // joined: rest of the pipeline on the default stream
    k_agg1<<<(NNODES + 7) / 8, 256>>>(We1, att1, b1);
    k_lin2_wmma<<<(NNODES + 63) / 64, 256>>>(bl2, br2);
    k_agg2_mlp<<<(NNODES + 7) / 8, 256>>>(We2, att2, b2, W1, c1, W2, c2, W3, c3, out);

    cudaEventDestroy(evFork);
    cudaEventDestroy(evJoin);
    cudaStreamDestroy(s2);
}

// round 16
// speedup vs baseline: 1.0989x; 1.0989x over previous
#include <cuda_runtime.h>
#include <cuda_fp16.h>
#include <mma.h>
#include <math.h>

#define NNODES 50000
#define NEDGES 800000
#define HC 128
#define SLOTS 64            // max degree capacity (Poisson λ=16; P(overflow) < 1e-8)
#define LOG2E 1.4426950408889634f

// ---------------- scratch (device globals; no allocation allowed) ----------
__device__ __align__(128) __half g_xl1h[NNODES * HC];  // gathered operand, fp16
__device__ __align__(128) float  g_xr1 [NNODES * HC];
__device__ __align__(128) __half g_h1h [NNODES * HC];  // layer-1 output (fp16, GEMM A)
__device__ __align__(128) __half g_xl2h[NNODES * HC];  // gathered operand, fp16
__device__ __align__(128) float  g_xr2 [NNODES * HC];
__device__ __align__(128) __half g_Wl2h[HC * HC];      // fp16 weights for HMMA
__device__ __align__(128) __half g_Wr2h[HC * HC];
// bucketed adjacency (built in ONE pass; no scan needed)
__device__ __align__(128) int   g_cnt[NNODES];         // per-node degree / cursor
__device__ __align__(128) int2  g_edge[NNODES * SLOTS];// (src, ea bits) per dst bucket

// ---------------- helpers ---------------------------------------------------
__device__ __forceinline__ float lrelu(float v) { return v >= 0.f ? v : 0.2f * v; }
__device__ __forceinline__ float eluf(float v)  { return v > 0.f ? v : expm1f(v); }

// load 4 halves (one uint2) and expand to float4
__device__ __forceinline__ float4 ld_half4(const __half* base, int idx4) {
    uint2 raw = ((const uint2*)base)[idx4];
    float2 lo = __half22float2(*(__half2*)&raw.x);
    float2 hi = __half22float2(*(__half2*)&raw.y);
    return make_float4(lo.x, lo.y, hi.x, hi.y);
}

// ---------------- bucket build ----------------------------------------------
__global__ void k_zero_cnt() {
    int i = blockIdx.x * blockDim.x + threadIdx.x;
    int i4 = i * 4;
    if (i4 + 3 < NNODES) {
        *(int4*)&g_cnt[i4] = make_int4(0, 0, 0, 0);
    } else if (i4 < NNODES) {
        for (int j = i4; j < NNODES; j++) g_cnt[j] = 0;
    }
}

// single pass: count + place (replaces hist + 3 scan stages + scatter)
__global__ void k_bucket(const int* __restrict__ ei, const float* __restrict__ ea) {
    int e = blockIdx.x * blockDim.x + threadIdx.x;
    if (e >= NEDGES) return;
    int d = ei[NEDGES + e];
    int pos = atomicAdd(&g_cnt[d], 1);
    g_edge[d * SLOTS + pos] = make_int2(ei[e], __float_as_int(ea[e]));
}

// ---------------- weight fp16 conversion (tiny) ------------------------------
__global__ void k_wcvt(const float* __restrict__ Wl, const float* __restrict__ Wr) {
    int i = blockIdx.x * blockDim.x + threadIdx.x;
    if (i < HC * HC) {
        g_Wl2h[i] = __float2half_rn(Wl[i]);
        g_Wr2h[i] = __float2half_rn(Wr[i]);
    }
}

// ---------------- layer 1 linear: x[N,16] -> xl1(fp16), xr1(fp32) ----------
// weights held in REGISTERS (32 per thread); smem only stages the x tile.
#define L1_NODES 32
__global__ __launch_bounds__(128) void k_lin1(
    const float* __restrict__ x,
    const float* __restrict__ Wl, const float* __restrict__ bl,
    const float* __restrict__ Wr, const float* __restrict__ br)
{
    __shared__ float xs[L1_NODES * 16];
    int tid = threadIdx.x;
    int nb = blockIdx.x * L1_NODES;

    // this thread's weight rows in registers
    float wl[16], wr[16];
    #pragma unroll
    for (int k = 0; k < 16; k += 4) {
        float4 v = *(const float4*)&Wl[tid * 16 + k];
        wl[k] = v.x; wl[k+1] = v.y; wl[k+2] = v.z; wl[k+3] = v.w;
        float4 u = *(const float4*)&Wr[tid * 16 + k];
        wr[k] = u.x; wr[k+1] = u.y; wr[k+2] = u.z; wr[k+3] = u.w;
    }
    float bL = bl[tid], bR = br[tid];

    // stage 32 nodes x 16 features = 128 float4
    {
        int node = nb + (tid >> 2);
        float4 v = make_float4(0.f, 0.f, 0.f, 0.f);
        if (node < NNODES) v = *(const float4*)&x[(long)node * 16 + (tid & 3) * 4];
        ((float4*)xs)[tid] = v;
    }
    __syncthreads();

    #pragma unroll 4
    for (int i = 0; i < L1_NODES; i++) {
        int n = nb + i;
        if (n >= NNODES) break;
        float aL = bL, aR = bR;
        #pragma unroll
        for (int k = 0; k < 16; k++) {
            float xv = xs[i * 16 + k];   // broadcast LDS
            aL += xv * wl[k];
            aR += xv * wr[k];
        }
        g_xl1h[(long)n * HC + tid] = __float2half_rn(aL);
        g_xr1 [(long)n * HC + tid] = aR;
    }
}

// ---------------- layer 1 aggregation: warp per dst node, 4-edge unroll -----
__global__ __launch_bounds__(256) void k_agg1(
    const float* __restrict__ We, const float* __restrict__ att,
    const float* __restrict__ b1)
{
    int n = blockIdx.x * 8 + (threadIdx.x >> 5);
    int t = threadIdx.x & 31;
    if (n >= NNODES) return;

    float4 b  = ((const float4*)g_xr1)[n * 32 + t];
    float4 wv = ((const float4*)We)[t];
    float4 av = ((const float4*)att)[t];
    av.x *= LOG2E; av.y *= LOG2E; av.z *= LOG2E; av.w *= LOG2E;

    float den = 0.f;
    float ax = 0.f, ay = 0.f, az = 0.f, aw = 0.f;

    int k0 = n * SLOTS, k1 = k0 + g_cnt[n];
    int k = k0;

    #define L1_LOGIT(a, e) \
        (lrelu(a.x + b.x + e * wv.x) * av.x + lrelu(a.y + b.y + e * wv.y) * av.y \
       + lrelu(a.z + b.z + e * wv.z) * av.z + lrelu(a.w + b.w + e * wv.w) * av.w)
    #define L1_RED(p) \
        p += __shfl_xor_sync(0xffffffffu, p, 4); \
        p += __shfl_xor_sync(0xffffffffu, p, 2); \
        p += __shfl_xor_sync(0xffffffffu, p, 1);

    for (; k + 3 < k1; k += 4) {
        int2 E0 = g_edge[k], E1 = g_edge[k+1], E2 = g_edge[k+2], E3 = g_edge[k+3];
        float eA = __int_as_float(E0.y), eB = __int_as_float(E1.y);
        float eC = __int_as_float(E2.y), eD = __int_as_float(E3.y);
        float4 a0 = ld_half4(g_xl1h, E0.x * 32 + t);
        float4 a1 = ld_half4(g_xl1h, E1.x * 32 + t);
        float4 a2 = ld_half4(g_xl1h, E2.x * 32 + t);
        float4 a3 = ld_half4(g_xl1h, E3.x * 32 + t);
        float p0 = L1_LOGIT(a0, eA);
        float p1 = L1_LOGIT(a1, eB);
        float p2 = L1_LOGIT(a2, eC);
        float p3 = L1_LOGIT(a3, eD);
        L1_RED(p0) L1_RED(p1) L1_RED(p2) L1_RED(p3)
        float e0 = exp2f(p0), e1 = exp2f(p1), e2 = exp2f(p2), e3 = exp2f(p3);
        den += (e0 + e1) + (e2 + e3);
        ax += e0 * a0.x + e1 * a1.x + e2 * a2.x + e3 * a3.x;
        ay += e0 * a0.y + e1 * a1.y + e2 * a2.y + e3 * a3.y;
        az += e0 * a0.z + e1 * a1.z + e2 * a2.z + e3 * a3.z;
        aw += e0 * a0.w + e1 * a1.w + e2 * a2.w + e3 * a3.w;
    }
    for (; k < k1; k++) {
        int2 E = g_edge[k];
        float e = __int_as_float(E.y);
        float4 a0 = ld_half4(g_xl1h, E.x * 32 + t);
        float p0 = L1_LOGIT(a0, e);
        L1_RED(p0)
        float e0 = exp2f(p0);
        den += e0;
        ax += e0 * a0.x; ay += e0 * a0.y; az += e0 * a0.z; aw += e0 * a0.w;
    }
    #undef L1_LOGIT
    #undef L1_RED

    float inv = den > 0.f ? 1.f / den : 0.f;
    float4 bb = ((const float4*)b1)[t];
    float o0 = eluf(ax * inv + bb.x);
    float o1 = eluf(ay * inv + bb.y);
    float o2 = eluf(az * inv + bb.z);
    float o3 = eluf(aw * inv + bb.w);
    __half2 ha = __floats2half2_rn(o0, o1);
    __half2 hb = __floats2half2_rn(o2, o3);
    uint2 pk;
    pk.x = *(unsigned*)&ha; pk.y = *(unsigned*)&hb;
    ((uint2*)g_h1h)[n * 32 + t] = pk;
}

// ---------------- layer 2 linear: HMMA (wmma) dual GEMM ---------------------
__global__ __launch_bounds__(256) void k_lin2_wmma(
    const float* __restrict__ bl, const float* __restrict__ br)
{
    using namespace nvcuda::wmma;
    __shared__ float slab[8][16][68];

    int warp = threadIdx.x >> 5, lane = threadIdx.x & 31;
    int rg = warp & 3, cg = warp >> 2;
    int row0 = blockIdx.x * 64 + rg * 16;
    if (row0 >= NNODES) return;        // NNODES % 16 == 0, frags never straddle
    int colbase = cg * 64;

    fragment<accumulator, 16, 16, 16, float> cL[4], cR[4];
    #pragma unroll
    for (int j = 0; j < 4; j++) { fill_fragment(cL[j], 0.f); fill_fragment(cR[j], 0.f); }

    #pragma unroll
    for (int k0 = 0; k0 < 128; k0 += 16) {
        fragment<matrix_a, 16, 16, 16, __half, row_major> a;
        load_matrix_sync(a, g_h1h + (long)row0 * 128 + k0, 128);
        #pragma unroll
        for (int j = 0; j < 4; j++) {
            fragment<matrix_b, 16, 16, 16, __half, col_major> bfrag;
            load_matrix_sync(bfrag, g_Wl2h + (long)(colbase + j * 16) * 128 + k0, 128);
            mma_sync(cL[j], a, bfrag, cL[j]);
            load_matrix_sync(bfrag, g_Wr2h + (long)(colbase + j * 16) * 128 + k0, 128);
            mma_sync(cR[j], a, bfrag, cR[j]);
        }
    }

    // epilogue L -> xl2 (fp16)
    #pragma unroll
    for (int j = 0; j < 4; j++)
        store_matrix_sync(&slab[warp][0][j * 16], cL[j], 68, mem_row_major);
    __syncwarp();
    for (int i = lane; i < 16 * 32; i += 32) {      // half2 elements
        int r = i >> 5, c2 = (i & 31) * 2;
        float v0 = slab[warp][r][c2]     + bl[colbase + c2];
        float v1 = slab[warp][r][c2 + 1] + bl[colbase + c2 + 1];
        __half2 h = __floats2half2_rn(v0, v1);
        *(__half2*)&g_xl2h[(long)(row0 + r) * 128 + colbase + c2] = h;
    }
    __syncwarp();

    // epilogue R -> xr2 (fp32)
    #pragma unroll
    for (int j = 0; j < 4; j++)
        store_matrix_sync(&slab[warp][0][j * 16], cR[j], 68, mem_row_major);
    __syncwarp();
    for (int i = lane; i < 16 * 32; i += 32) {      // float2 elements
        int r = i >> 5, c2 = (i & 31) * 2;
        float2 v;
        v.x = slab[warp][r][c2]     + br[colbase + c2];
        v.y = slab[warp][r][c2 + 1] + br[colbase + c2 + 1];
        *(float2*)&g_xr2[(long)(row0 + r) * 128 + colbase + c2] = v;
    }
}

// ---------------- layer 2 aggregation + MLP head, fused (warp per node) -----
__global__ __launch_bounds__(256) void k_agg2_mlp(
    const float* __restrict__ We, const float* __restrict__ att,
    const float* __restrict__ b2,
    const float* __restrict__ W1, const float* __restrict__ c1,
    const float* __restrict__ W2, const float* __restrict__ c2,
    const float* __restrict__ W3, const float* __restrict__ c3,
    float* __restrict__ out)
{
    __shared__ float sW1[32][129];
    __shared__ float sW2[32][33];
    __shared__ float sW3[2][32];
    __shared__ float sh[8][128];
    int tid = threadIdx.x;
    for (int i = tid; i < 32 * 128; i += 256) sW1[i >> 7][i & 127] = W1[i];
    for (int i = tid; i < 32 * 32; i += 256) sW2[i >> 5][i & 31] = W2[i];
    if (tid < 64) sW3[tid >> 5][tid & 31] = W3[tid];
    __syncthreads();

    int w = tid >> 5, t = tid & 31;
    int n = blockIdx.x * 8 + w;
    if (n >= NNODES) return;

    float4 b  = ((const float4*)g_xr2)[n * 32 + t];
    float4 wv = ((const float4*)We)[t];
    float4 av = ((const float4*)att)[t];
    av.x *= LOG2E; av.y *= LOG2E; av.z *= LOG2E; av.w *= LOG2E;

    float den = 0.f;
    float ax = 0.f, ay = 0.f, az = 0.f, aw = 0.f;

    int k0 = n * SLOTS, k1 = k0 + g_cnt[n];
    int k = k0;

    #define L2_LOGIT(a, e) \
        (lrelu(a.x + b.x + e * wv.x) * av.x + lrelu(a.y + b.y + e * wv.y) * av.y \
       + lrelu(a.z + b.z + e * wv.z) * av.z + lrelu(a.w + b.w + e * wv.w) * av.w)
    #define L2_RED(p) { \
        p += __shfl_xor_sync(0xffffffffu, p, 16); \
        p += __shfl_xor_sync(0xffffffffu, p, 8); \
        p += __shfl_xor_sync(0xffffffffu, p, 4); \
        p += __shfl_xor_sync(0xffffffffu, p, 2); \
        p += __shfl_xor_sync(0xffffffffu, p, 1); }

    for (; k + 3 < k1; k += 4) {
        int2 E0 = g_edge[k], E1 = g_edge[k+1], E2 = g_edge[k+2], E3 = g_edge[k+3];
        float eA = __int_as_float(E0.y), eB = __int_as_float(E1.y);
        float eC = __int_as_float(E2.y), eD = __int_as_float(E3.y);
        float4 a0 = ld_half4(g_xl2h, E0.x * 32 + t);
        float4 a1 = ld_half4(g_xl2h, E1.x * 32 + t);
        float4 a2 = ld_half4(g_xl2h, E2.x * 32 + t);
        float4 a3 = ld_half4(g_xl2h, E3.x * 32 + t);
        float p0 = L2_LOGIT(a0, eA);
        float p1 = L2_LOGIT(a1, eB);
        float p2 = L2_LOGIT(a2, eC);
        float p3 = L2_LOGIT(a3, eD);
        L2_RED(p0) L2_RED(p1) L2_RED(p2) L2_RED(p3)
        float e0 = exp2f(p0), e1 = exp2f(p1), e2 = exp2f(p2), e3 = exp2f(p3);
        den += (e0 + e1) + (e2 + e3);
        ax += e0 * a0.x + e1 * a1.x + e2 * a2.x + e3 * a3.x;
        ay += e0 * a0.y + e1 * a1.y + e2 * a2.y + e3 * a3.y;
        az += e0 * a0.z + e1 * a1.z + e2 * a2.z + e3 * a3.z;
        aw += e0 * a0.w + e1 * a1.w + e2 * a2.w + e3 * a3.w;
    }
    for (; k < k1; k++) {
        int2 E = g_edge[k];
        float e = __int_as_float(E.y);
        float4 a0 = ld_half4(g_xl2h, E.x * 32 + t);
        float p0 = L2_LOGIT(a0, e);
        L2_RED(p0)
        float e0 = exp2f(p0);
        den += e0;
        ax += e0 * a0.x; ay += e0 * a0.y; az += e0 * a0.z; aw += e0 * a0.w;
    }
    #undef L2_LOGIT
    #undef L2_RED

    float inv = den > 0.f ? 1.f / den : 0.f;
    float4 bb = ((const float4*)b2)[t];
    sh[w][t * 4 + 0] = eluf(ax * inv + bb.x);
    sh[w][t * 4 + 1] = eluf(ay * inv + bb.y);
    sh[w][t * 4 + 2] = eluf(az * inv + bb.z);
    sh[w][t * 4 + 3] = eluf(aw * inv + bb.w);
    __syncwarp();

    float t1 = c1[t];
    #pragma unroll
    for (int kk = 0; kk < 128; kk++) t1 += sh[w][kk] * sW1[t][kk];
    t1 = fmaxf(t1, 0.f);

    float t2 = c2[t];
    #pragma unroll
    for (int kk = 0; kk < 32; kk++) t2 += __shfl_sync(0xffffffffu, t1, kk) * sW2[t][kk];
    t2 = fmaxf(t2, 0.f);

    float s0 = t2 * sW3[0][t];
    float s1 = t2 * sW3[1][t];
    #pragma unroll
    for (int o = 16; o; o >>= 1) {
        s0 += __shfl_down_sync(0xffffffffu, s0, o);
        s1 += __shfl_down_sync(0xffffffffu, s1, o);
    }
    if (t == 0) {
        out[(long)n * 2 + 0] = s0 + c3[0];
        out[(long)n * 2 + 1] = s1 + c3[1];
    }
}

// ---------------- launch ----------------------------------------------------
extern "C" void kernel_launch(void* const* d_in, const int* in_sizes, int n_in,
                              void* d_out, int out_size)
{
    const float* x    = (const float*)d_in[0];
    const int*   ei   = (const int*)d_in[1];
    const float* ea   = (const float*)d_in[2];
    const float* Wl1  = (const float*)d_in[3];
    const float* bl1  = (const float*)d_in[4];
    const float* Wr1  = (const float*)d_in[5];
    const float* br1  = (const float*)d_in[6];
    const float* We1  = (const float*)d_in[7];
    const float* att1 = (const float*)d_in[8];
    const float* b1   = (const float*)d_in[9];
    const float* Wl2  = (const float*)d_in[10];
    const float* bl2  = (const float*)d_in[11];
    const float* Wr2  = (const float*)d_in[12];
    const float* br2  = (const float*)d_in[13];
    const float* We2  = (const float*)d_in[14];
    const float* att2 = (const float*)d_in[15];
    const float* b2   = (const float*)d_in[16];
    const float* W1   = (const float*)d_in[17];
    const float* c1   = (const float*)d_in[18];
    const float* W2   = (const float*)d_in[19];
    const float* c2   = (const float*)d_in[20];
    const float* W3   = (const float*)d_in[21];
    const float* c3   = (const float*)d_in[22];
    float* out = (float*)d_out;

    // fork a side stream: bucket build (default stream) || wcvt+lin1 (side)
    cudaStream_t s2;
    cudaStreamCreateWithFlags(&s2, cudaStreamNonBlocking);
    cudaEvent_t evFork, evJoin;
    cudaEventCreateWithFlags(&evFork, cudaEventDisableTiming);
    cudaEventCreateWithFlags(&evJoin, cudaEventDisableTiming);

    cudaEventRecord(evFork, 0);
    cudaStreamWaitEvent(s2, evFork, 0);

    // bucket build on the capture-origin (default) stream: 2 launches total
    k_zero_cnt<<<(NNODES / 4 + 255) / 256, 256>>>();
    k_bucket<<<(NEDGES + 255) / 256, 256>>>(ei, ea);

    // independent work on the side stream
    k_wcvt<<<(HC * HC + 255) / 256, 256, 0, s2>>>(Wl2, Wr2);
    k_lin1<<<(NNODES + L1_NODES - 1) / L1_NODES, 128, 0, s2>>>(x, Wl1, bl1, Wr1, br1);

    cudaEventRecord(evJoin, s2);
    cudaStreamWaitEvent(0, evJoin, 0);

    // joined: rest of the pipeline on the default stream
    k_agg1<<<(NNODES + 7) / 8, 256>>>(We1, att1, b1);
    k_lin2_wmma<<<(NNODES + 63) / 64, 256>>>(bl2, br2);
    k_agg2_mlp<<<(NNODES + 7) / 8, 256>>>(We2, att2, b2, W1, c1, W2, c2, W3, c3, out);

    cudaEventDestroy(evFork);
    cudaEventDestroy(evJoin);
    cudaStreamDestroy(s2);
}